// round 14
// baseline (speedup 1.0000x reference)
#include <cuda_runtime.h>
#include <cuda_bf16.h>
#include <cstdint>

// ---------------------------------------------------------------------------
// Problem constants
// ---------------------------------------------------------------------------
#define PHM      4
#define IN_FEATS 2048
#define OUT_FEATS 8192
#define TOKENS   8192
#define IN_PER   (IN_FEATS / PHM)    // 512
#define OUT_PER  (OUT_FEATS / PHM)   // 2048

// ---------------------------------------------------------------------------
// Static device scratch (allowed; no dynamic allocation)
// ---------------------------------------------------------------------------
__device__ __nv_bfloat16 g_xhi[(size_t)TOKENS * IN_FEATS];
__device__ __nv_bfloat16 g_xlo[(size_t)TOKENS * IN_FEATS];
__device__ __nv_bfloat16 g_Hthi[(size_t)OUT_FEATS * IN_FEATS];  // H^T [n][k]
__device__ __nv_bfloat16 g_Htlo[(size_t)OUT_FEATS * IN_FEATS];

// ---------------------------------------------------------------------------
// Helpers (only non-arch-suffixed PTX: cp.async sm_80, ldmatrix sm_75,
// mma.sync bf16 sm_80 — all legal on plain compute_103)
// ---------------------------------------------------------------------------
__device__ __forceinline__ uint32_t smem_to_u32(const void* p) {
    uint32_t a;
    asm("{ .reg .u64 t; cvta.to.shared.u64 t, %1; cvt.u32.u64 %0, t; }"
        : "=r"(a) : "l"(p));
    return a;
}

#define SMEM_SWIZZLE_128B(o) ((o) ^ (((o) >> 3) & 0x70))

#define CP_ASYNC16(smem_addr, gptr) \
    asm volatile("cp.async.cg.shared.global [%0], [%1], 16;" \
                 :: "r"((uint32_t)(smem_addr)), "l"(gptr) : "memory")
#define CP_ASYNC_COMMIT() asm volatile("cp.async.commit_group;" ::: "memory")

#define LDSM_X4(r0, r1, r2, r3, addr) \
    asm volatile("ldmatrix.sync.aligned.m8n8.x4.shared.b16 {%0,%1,%2,%3}, [%4];" \
                 : "=r"(r0), "=r"(r1), "=r"(r2), "=r"(r3) : "r"(addr))

#define MMA_BF16(d, a, b0, b1) \
    asm volatile("mma.sync.aligned.m16n8k16.row.col.f32.bf16.bf16.f32 " \
                 "{%0,%1,%2,%3}, {%4,%5,%6,%7}, {%8,%9}, {%0,%1,%2,%3};" \
                 : "+f"((d)[0]), "+f"((d)[1]), "+f"((d)[2]), "+f"((d)[3]) \
                 : "r"((a)[0]), "r"((a)[1]), "r"((a)[2]), "r"((a)[3]), \
                   "r"(b0), "r"(b1))

// ---------------------------------------------------------------------------
// Kernel 1: split x into bf16 hi/lo
// ---------------------------------------------------------------------------
__global__ __launch_bounds__(256) void split_x_kernel(const float* __restrict__ x) {
    const size_t i = (size_t)blockIdx.x * 256 + threadIdx.x;  // float4 index
    const float4 v = reinterpret_cast<const float4*>(x)[i];

    __nv_bfloat16 h0 = __float2bfloat16(v.x);
    __nv_bfloat16 h1 = __float2bfloat16(v.y);
    __nv_bfloat16 h2 = __float2bfloat16(v.z);
    __nv_bfloat16 h3 = __float2bfloat16(v.w);
    __nv_bfloat16 l0 = __float2bfloat16(v.x - __bfloat162float(h0));
    __nv_bfloat16 l1 = __float2bfloat16(v.y - __bfloat162float(h1));
    __nv_bfloat16 l2 = __float2bfloat16(v.z - __bfloat162float(h2));
    __nv_bfloat16 l3 = __float2bfloat16(v.w - __bfloat162float(h3));

    __nv_bfloat162* ph = reinterpret_cast<__nv_bfloat162*>(g_xhi);
    __nv_bfloat162* pl = reinterpret_cast<__nv_bfloat162*>(g_xlo);
    ph[2 * i]     = __nv_bfloat162(h0, h1);
    ph[2 * i + 1] = __nv_bfloat162(h2, h3);
    pl[2 * i]     = __nv_bfloat162(l0, l1);
    pl[2 * i + 1] = __nv_bfloat162(l2, l3);
}

// ---------------------------------------------------------------------------
// Kernel 2: build H^T in bf16 hi/lo.
//   H[r, n] = sum_i rule[i, a, k] * W[i, c, p],  r=a*512+c, n=k*2048+p
// ---------------------------------------------------------------------------
__global__ __launch_bounds__(256) void build_Ht_kernel(
    const float* __restrict__ rule,   // (4,4,4)
    const float* __restrict__ W)      // (4,512,2048)
{
    __shared__ float hs[64][65];

    const int n0 = blockIdx.x * 64;   // over OUT_FEATS
    const int r0 = blockIdx.y * 64;   // over IN_FEATS
    const int a = r0 >> 9;
    const int k = n0 >> 11;

    const float s0 = rule[0 * 16 + a * 4 + k];
    const float s1 = rule[1 * 16 + a * 4 + k];
    const float s2 = rule[2 * 16 + a * 4 + k];
    const float s3 = rule[3 * 16 + a * 4 + k];

    {
        const int nl = threadIdx.x & 63;
        const int rg = threadIdx.x >> 6;    // 0..3
        const int p = (n0 & 2047) + nl;
        const int cbase = (r0 & 511);
#pragma unroll
        for (int j = 0; j < 16; j++) {
            const int rl = rg * 16 + j;
            const int c = cbase + rl;
            float acc = s0 * W[(size_t)(0 * IN_PER + c) * OUT_PER + p]
                      + s1 * W[(size_t)(1 * IN_PER + c) * OUT_PER + p]
                      + s2 * W[(size_t)(2 * IN_PER + c) * OUT_PER + p]
                      + s3 * W[(size_t)(3 * IN_PER + c) * OUT_PER + p];
            hs[rl][nl] = acc;
        }
    }
    __syncthreads();
    {
        const int rl = threadIdx.x & 63;
        const int ng = threadIdx.x >> 6;
#pragma unroll
        for (int j = 0; j < 16; j++) {
            const int nn = ng * 16 + j;
            const float v = hs[rl][nn];
            const __nv_bfloat16 hi = __float2bfloat16(v);
            const __nv_bfloat16 lo = __float2bfloat16(v - __bfloat162float(hi));
            const size_t o = (size_t)(n0 + nn) * IN_FEATS + r0 + rl;
            g_Hthi[o] = hi;
            g_Htlo[o] = lo;
        }
    }
}

// ---------------------------------------------------------------------------
// Kernel 3: HMMA GEMM (mma.sync bf16), y = x @ H + b, double-bf16 3-product.
//   CTA tile 128x256, KC=32, 3-stage cp.async pipeline, 512 threads.
//   16 warps, warp tile 64x32 -> 64 accum regs/thread, 4 warps/SMSP.
//   MMA order: product-outermost so consecutive MMAs hit different
//   accumulators (no 3-deep RAW chains).
//   smem row layout (128B/row, SW128 swizzle): [hi k0..31 | lo k0..31]
// ---------------------------------------------------------------------------
#define BM 128
#define BN 256
#define KC 32
#define NSTAGE 3
#define NTHREADS 512
#define NCHUNK (IN_FEATS / KC)              // 64
#define SM_B_OFF (BM * 128)                 // 16 KB: B region after A region
#define STAGE_BYTES ((BM + BN) * 128)       // 48 KB
#define SMEM_TOTAL_GEMM (NSTAGE * STAGE_BYTES)  // 144 KB

__global__ __launch_bounds__(NTHREADS, 1) void phm_mma_kernel(
    const float* __restrict__ bias,
    float* __restrict__ C)
{
    extern __shared__ char smem[];
    const uint32_t sbase = smem_to_u32(smem);
    const int tid = threadIdx.x;
    const int lid = tid & 31;
    const int wid = tid >> 5;
    const int warp_m = wid & 1;       // 2 warps over M (64 rows each)
    const int warp_n = wid >> 1;      // 8 warps over N (32 cols each)

    const int mrow0 = blockIdx.x * BM;
    const int ncol0 = blockIdx.y * BN;

    float acc[4][4][4];               // [mt][nb(8col)][frag]
#pragma unroll
    for (int i = 0; i < 4; i++)
#pragma unroll
        for (int j = 0; j < 4; j++)
#pragma unroll
            for (int e = 0; e < 4; e++) acc[i][j][e] = 0.f;

    // ---- stage loader (A: 1024 16B chunks, B: 2048 16B chunks; 512 thr) ----
#define LOAD_STAGE(sptr, c) do {                                              \
    const int _kc0 = (c) * KC;                                                \
    _Pragma("unroll")                                                         \
    for (int _j = 0; _j < 2; _j++) {                                          \
        const int _q = tid + NTHREADS * _j;                                   \
        const int _row = _q >> 3; const int _u = _q & 7;                      \
        const uint32_t _so = (sptr) +                                         \
            SMEM_SWIZZLE_128B((uint32_t)(_row * 128 + _u * 16));              \
        const __nv_bfloat16* _src = (_u < 4)                                  \
            ? (g_xhi + (size_t)(mrow0 + _row) * IN_FEATS + _kc0 + _u * 8)     \
            : (g_xlo + (size_t)(mrow0 + _row) * IN_FEATS + _kc0 + (_u - 4) * 8); \
        CP_ASYNC16(_so, _src);                                                \
    }                                                                         \
    _Pragma("unroll")                                                         \
    for (int _j = 0; _j < 4; _j++) {                                          \
        const int _q = tid + NTHREADS * _j;                                   \
        const int _row = _q >> 3; const int _u = _q & 7;                      \
        const uint32_t _so = (sptr) + SM_B_OFF +                              \
            SMEM_SWIZZLE_128B((uint32_t)(_row * 128 + _u * 16));              \
        const __nv_bfloat16* _src = (_u < 4)                                  \
            ? (g_Hthi + (size_t)(ncol0 + _row) * IN_FEATS + _kc0 + _u * 8)    \
            : (g_Htlo + (size_t)(ncol0 + _row) * IN_FEATS + _kc0 + (_u - 4) * 8); \
        CP_ASYNC16(_so, _src);                                                \
    }                                                                         \
    CP_ASYNC_COMMIT();                                                        \
} while (0)

    // Prologue: fill stages 0 and 1
    LOAD_STAGE(sbase + 0 * STAGE_BYTES, 0);
    LOAD_STAGE(sbase + 1 * STAGE_BYTES, 1);

    // Lane-constant fragment addressing pieces
    const int a_row_l = lid & 15;
    const int a_k16   = (lid >> 4) * 16;
    const int b_row_l = ((lid >> 4) << 3) + (lid & 7);
    const int b_k16   = ((lid >> 3) & 1) * 16;

    int sidx = 0;
    for (int c = 0; c < NCHUNK; c++) {
        if (c + 1 < NCHUNK) {
            asm volatile("cp.async.wait_group 1;" ::: "memory");
        } else {
            asm volatile("cp.async.wait_group 0;" ::: "memory");
        }
        __syncthreads();

        if (c + 2 < NCHUNK) {
            const int ns = (sidx + 2 >= NSTAGE) ? (sidx + 2 - NSTAGE) : (sidx + 2);
            LOAD_STAGE(sbase + ns * STAGE_BYTES, c + 2);
        }

        const uint32_t abase = sbase + sidx * STAGE_BYTES;
        const uint32_t bbase = abase + SM_B_OFF;

#pragma unroll
        for (int ks = 0; ks < 2; ks++) {   // two K=16 steps per KC=32 chunk
            uint32_t ah[4][4], al[4][4], bh[2][4], bl[2][4];

            // --- load hi fragments, run hi*hi ---
#pragma unroll
            for (int mt = 0; mt < 4; mt++) {
                const int row = warp_m * 64 + mt * 16 + a_row_l;
                const uint32_t byte = (uint32_t)(row * 128 + ks * 32 + a_k16);
                LDSM_X4(ah[mt][0], ah[mt][1], ah[mt][2], ah[mt][3],
                        abase + SMEM_SWIZZLE_128B(byte));
            }
#pragma unroll
            for (int ng = 0; ng < 2; ng++) {
                const int row = warp_n * 32 + ng * 16 + b_row_l;
                const uint32_t byte = (uint32_t)(row * 128 + ks * 32 + b_k16);
                LDSM_X4(bh[ng][0], bh[ng][1], bh[ng][2], bh[ng][3],
                        bbase + SMEM_SWIZZLE_128B(byte));
            }
#pragma unroll
            for (int mt = 0; mt < 4; mt++)
#pragma unroll
                for (int ng = 0; ng < 2; ng++)
#pragma unroll
                    for (int h = 0; h < 2; h++)
                        MMA_BF16(acc[mt][ng * 2 + h], ah[mt],
                                 bh[ng][2 * h], bh[ng][2 * h + 1]);

            // --- load A-lo, run lo*hi (bh reused) ---
#pragma unroll
            for (int mt = 0; mt < 4; mt++) {
                const int row = warp_m * 64 + mt * 16 + a_row_l;
                const uint32_t byte = (uint32_t)(row * 128 + ks * 32 + a_k16);
                LDSM_X4(al[mt][0], al[mt][1], al[mt][2], al[mt][3],
                        abase + SMEM_SWIZZLE_128B(byte + 64));
            }
#pragma unroll
            for (int mt = 0; mt < 4; mt++)
#pragma unroll
                for (int ng = 0; ng < 2; ng++)
#pragma unroll
                    for (int h = 0; h < 2; h++)
                        MMA_BF16(acc[mt][ng * 2 + h], al[mt],
                                 bh[ng][2 * h], bh[ng][2 * h + 1]);

            // --- load B-lo, run hi*lo (ah reused) ---
#pragma unroll
            for (int ng = 0; ng < 2; ng++) {
                const int row = warp_n * 32 + ng * 16 + b_row_l;
                const uint32_t byte = (uint32_t)(row * 128 + ks * 32 + b_k16);
                LDSM_X4(bl[ng][0], bl[ng][1], bl[ng][2], bl[ng][3],
                        bbase + SMEM_SWIZZLE_128B(byte + 64));
            }
#pragma unroll
            for (int mt = 0; mt < 4; mt++)
#pragma unroll
                for (int ng = 0; ng < 2; ng++)
#pragma unroll
                    for (int h = 0; h < 2; h++)
                        MMA_BF16(acc[mt][ng * 2 + h], ah[mt],
                                 bl[ng][2 * h], bl[ng][2 * h + 1]);
        }
        __syncthreads();
        sidx = (sidx + 1 == NSTAGE) ? 0 : sidx + 1;
    }

    // ---- Epilogue: bias + store (float2, coalesced per quad) ----
    const int qrow = lid >> 2;            // 0..7
    const int qcol = (lid & 3) * 2;       // 0,2,4,6
#pragma unroll
    for (int mt = 0; mt < 4; mt++) {
        const int r0 = mrow0 + warp_m * 64 + mt * 16 + qrow;
#pragma unroll
        for (int nb = 0; nb < 4; nb++) {
            const int col = ncol0 + warp_n * 32 + nb * 8 + qcol;
            const float2 bb = *reinterpret_cast<const float2*>(&bias[col]);
            float2 o0, o1;
            o0.x = acc[mt][nb][0] + bb.x;
            o0.y = acc[mt][nb][1] + bb.y;
            o1.x = acc[mt][nb][2] + bb.x;
            o1.y = acc[mt][nb][3] + bb.y;
            *reinterpret_cast<float2*>(&C[(size_t)r0 * OUT_FEATS + col]) = o0;
            *reinterpret_cast<float2*>(&C[(size_t)(r0 + 8) * OUT_FEATS + col]) = o1;
        }
    }
#undef LOAD_STAGE
}

// ---------------------------------------------------------------------------
// Launch: inputs per metadata order: x, phm_rule, W, b. Output float32.
// ---------------------------------------------------------------------------
extern "C" void kernel_launch(void* const* d_in, const int* in_sizes, int n_in,
                              void* d_out, int out_size) {
    const float* x    = (const float*)d_in[0];
    const float* rule = (const float*)d_in[1];
    const float* W    = (const float*)d_in[2];
    const float* b    = (const float*)d_in[3];
    float* y = (float*)d_out;
    (void)in_sizes; (void)n_in; (void)out_size;

    cudaFuncSetAttribute(phm_mma_kernel,
                         cudaFuncAttributeMaxDynamicSharedMemorySize,
                         SMEM_TOTAL_GEMM);

    // 1) split x into bf16 hi/lo
    {
        const int total4 = (TOKENS * IN_FEATS) / 4;
        split_x_kernel<<<total4 / 256, 256>>>(x);
    }
    // 2) build H^T bf16 hi/lo
    {
        dim3 grid(OUT_FEATS / 64, IN_FEATS / 64);   // (128, 32)
        build_Ht_kernel<<<grid, 256>>>(rule, W);
    }
    // 3) HMMA GEMM + bias.  blockIdx.x = M (fast) -> wave shares the N tile's
    //    B data in L2; A streams through.
    {
        dim3 grid(TOKENS / BM, OUT_FEATS / BN);     // (64, 32)
        phm_mma_kernel<<<grid, NTHREADS, SMEM_TOTAL_GEMM>>>(b, y);
    }
}

// round 15
// speedup vs baseline: 1.5788x; 1.5788x over previous
#include <cuda_runtime.h>
#include <cuda_bf16.h>
#include <cstdint>

// ---------------------------------------------------------------------------
// Problem constants
// ---------------------------------------------------------------------------
#define PHM      4
#define IN_FEATS 2048
#define OUT_FEATS 8192
#define TOKENS   8192
#define IN_PER   (IN_FEATS / PHM)    // 512
#define OUT_PER  (OUT_FEATS / PHM)   // 2048

// ---------------------------------------------------------------------------
// Static device scratch: tf32-rounded (rna) fp32 copies of x and H^T.
// ---------------------------------------------------------------------------
__device__ float g_xt[(size_t)TOKENS * IN_FEATS];                // 64 MB
__device__ float g_Ht[(size_t)OUT_FEATS * IN_FEATS];             // 64 MB, H^T [n][k]

// ---------------------------------------------------------------------------
// Helpers (non-arch-suffixed PTX only: cp.async sm80, ldmatrix sm75,
// mma tf32 sm80, cvt.rna.tf32 sm80 — all legal on plain compute_103)
// ---------------------------------------------------------------------------
__device__ __forceinline__ uint32_t smem_to_u32(const void* p) {
    uint32_t a;
    asm("{ .reg .u64 t; cvta.to.shared.u64 t, %1; cvt.u32.u64 %0, t; }"
        : "=r"(a) : "l"(p));
    return a;
}

__device__ __forceinline__ float f2tf32(float f) {
    float r;
    asm("cvt.rna.tf32.f32 %0, %1;" : "=f"(r) : "f"(f));
    return r;
}

#define SMEM_SWIZZLE_128B(o) ((o) ^ (((o) >> 3) & 0x70))

#define CP_ASYNC16(smem_addr, gptr) \
    asm volatile("cp.async.cg.shared.global [%0], [%1], 16;" \
                 :: "r"((uint32_t)(smem_addr)), "l"(gptr) : "memory")
#define CP_ASYNC_COMMIT() asm volatile("cp.async.commit_group;" ::: "memory")

#define LDSM_X4(r0, r1, r2, r3, addr) \
    asm volatile("ldmatrix.sync.aligned.m8n8.x4.shared.b16 {%0,%1,%2,%3}, [%4];" \
                 : "=r"(r0), "=r"(r1), "=r"(r2), "=r"(r3) : "r"(addr))

// m16n8k8 tf32 MMA: a = 4 regs, b = 2 regs, fp32 accumulate
#define MMA_TF32(d, a, b0, b1) \
    asm volatile("mma.sync.aligned.m16n8k8.row.col.f32.tf32.tf32.f32 " \
                 "{%0,%1,%2,%3}, {%4,%5,%6,%7}, {%8,%9}, {%0,%1,%2,%3};" \
                 : "+f"((d)[0]), "+f"((d)[1]), "+f"((d)[2]), "+f"((d)[3]) \
                 : "r"((a)[0]), "r"((a)[1]), "r"((a)[2]), "r"((a)[3]), \
                   "r"(b0), "r"(b1))

// ---------------------------------------------------------------------------
// Kernel 1: round x to tf32 (rna) — operands must be pre-rounded because the
// MMA's internal mantissa truncation is biased (would cost ~1e-3 alone).
// ---------------------------------------------------------------------------
__global__ __launch_bounds__(256) void cvt_x_kernel(const float* __restrict__ x) {
    const size_t i = (size_t)blockIdx.x * 256 + threadIdx.x;  // float4 index
    const float4 v = reinterpret_cast<const float4*>(x)[i];
    float4 o;
    o.x = f2tf32(v.x); o.y = f2tf32(v.y); o.z = f2tf32(v.z); o.w = f2tf32(v.w);
    reinterpret_cast<float4*>(g_xt)[i] = o;
}

// ---------------------------------------------------------------------------
// Kernel 2: build H^T, tf32-rounded fp32.
//   H[r, n] = sum_i rule[i, a, k] * W[i, c, p],  r=a*512+c, n=k*2048+p
//   H^T stored (OUT_FEATS x IN_FEATS) row-major: row=n, col=r.
// ---------------------------------------------------------------------------
__global__ __launch_bounds__(256) void build_Ht_kernel(
    const float* __restrict__ rule,   // (4,4,4)
    const float* __restrict__ W)      // (4,512,2048)
{
    __shared__ float hs[64][65];

    const int n0 = blockIdx.x * 64;   // over OUT_FEATS
    const int r0 = blockIdx.y * 64;   // over IN_FEATS
    const int a = r0 >> 9;
    const int k = n0 >> 11;

    const float s0 = rule[0 * 16 + a * 4 + k];
    const float s1 = rule[1 * 16 + a * 4 + k];
    const float s2 = rule[2 * 16 + a * 4 + k];
    const float s3 = rule[3 * 16 + a * 4 + k];

    {
        const int nl = threadIdx.x & 63;
        const int rg = threadIdx.x >> 6;    // 0..3
        const int p = (n0 & 2047) + nl;
        const int cbase = (r0 & 511);
#pragma unroll
        for (int j = 0; j < 16; j++) {
            const int rl = rg * 16 + j;
            const int c = cbase + rl;
            float acc = s0 * W[(size_t)(0 * IN_PER + c) * OUT_PER + p]
                      + s1 * W[(size_t)(1 * IN_PER + c) * OUT_PER + p]
                      + s2 * W[(size_t)(2 * IN_PER + c) * OUT_PER + p]
                      + s3 * W[(size_t)(3 * IN_PER + c) * OUT_PER + p];
            hs[rl][nl] = acc;
        }
    }
    __syncthreads();
    {
        const int rl = threadIdx.x & 63;
        const int ng = threadIdx.x >> 6;
#pragma unroll
        for (int j = 0; j < 16; j++) {
            const int nn = ng * 16 + j;
            g_Ht[(size_t)(n0 + nn) * IN_FEATS + r0 + rl] = f2tf32(hs[rl][nn]);
        }
    }
}

// ---------------------------------------------------------------------------
// Kernel 3: tf32 MMA GEMM, y = x @ H + b (single pass).
//   CTA tile 128x256, KC=32 (4 k8 steps), 3-stage cp.async, 256 threads.
//   8 warps, warp tile 64x64 (R12-proven shape; only the MMA dtype changed).
//   smem rows: 32 tf32 = 128B, SW128-swizzled.
// ---------------------------------------------------------------------------
#define BM 128
#define BN 256
#define KC 32
#define NSTAGE 3
#define NTHREADS 256
#define NCHUNK (IN_FEATS / KC)              // 64
#define SM_B_OFF (BM * 128)                 // 16 KB
#define STAGE_BYTES ((BM + BN) * 128)       // 48 KB
#define SMEM_TOTAL_GEMM (NSTAGE * STAGE_BYTES)  // 144 KB

__global__ __launch_bounds__(NTHREADS, 1) void phm_mma_kernel(
    const float* __restrict__ bias,
    float* __restrict__ C)
{
    extern __shared__ char smem[];
    const uint32_t sbase = smem_to_u32(smem);
    const int tid = threadIdx.x;
    const int lid = tid & 31;
    const int wid = tid >> 5;
    const int warp_m = wid & 1;       // 2 warps over M (64 rows each)
    const int warp_n = wid >> 1;      // 4 warps over N (64 cols each)

    const int mrow0 = blockIdx.x * BM;
    const int ncol0 = blockIdx.y * BN;

    float acc[4][8][4];               // [mt][n8-group][frag]
#pragma unroll
    for (int i = 0; i < 4; i++)
#pragma unroll
        for (int j = 0; j < 8; j++)
#pragma unroll
            for (int e = 0; e < 4; e++) acc[i][j][e] = 0.f;

    // ---- stage loader: A 128 rows x 128B, B 256 rows x 128B (16B units) ----
#define LOAD_STAGE(sptr, c) do {                                              \
    const int _kc0 = (c) * KC;                                                \
    _Pragma("unroll")                                                         \
    for (int _j = 0; _j < 4; _j++) {                                          \
        const int _q = tid + NTHREADS * _j;                                   \
        const int _row = _q >> 3; const int _u = _q & 7;                      \
        const uint32_t _so = (sptr) +                                         \
            SMEM_SWIZZLE_128B((uint32_t)(_row * 128 + _u * 16));              \
        CP_ASYNC16(_so, g_xt + (size_t)(mrow0 + _row) * IN_FEATS + _kc0 + _u * 4); \
    }                                                                         \
    _Pragma("unroll")                                                         \
    for (int _j = 0; _j < 8; _j++) {                                          \
        const int _q = tid + NTHREADS * _j;                                   \
        const int _row = _q >> 3; const int _u = _q & 7;                      \
        const uint32_t _so = (sptr) + SM_B_OFF +                              \
            SMEM_SWIZZLE_128B((uint32_t)(_row * 128 + _u * 16));              \
        CP_ASYNC16(_so, g_Ht + (size_t)(ncol0 + _row) * IN_FEATS + _kc0 + _u * 4); \
    }                                                                         \
    CP_ASYNC_COMMIT();                                                        \
} while (0)

    // Prologue
    LOAD_STAGE(sbase + 0 * STAGE_BYTES, 0);
    LOAD_STAGE(sbase + 1 * STAGE_BYTES, 1);

    // ldmatrix lane addressing (b32-tile interpretation of m8n8.b16 tiles):
    // A frag (16 rows x k8): lanes 0-15 rows, +16B for k4-7 half.
    const int a_row_l = lid & 15;
    const int a_k16   = (lid >> 4) * 16;
    // B frag pair (16 n x k8): lanes supply n rows / k halves.
    const int b_row_l = ((lid >> 4) << 3) + (lid & 7);
    const int b_k16   = ((lid >> 3) & 1) * 16;

    int sidx = 0;
    for (int c = 0; c < NCHUNK; c++) {
        if (c + 1 < NCHUNK) {
            asm volatile("cp.async.wait_group 1;" ::: "memory");
        } else {
            asm volatile("cp.async.wait_group 0;" ::: "memory");
        }
        __syncthreads();

        if (c + 2 < NCHUNK) {
            const int ns = (sidx + 2 >= NSTAGE) ? (sidx + 2 - NSTAGE) : (sidx + 2);
            LOAD_STAGE(sbase + ns * STAGE_BYTES, c + 2);
        }

        const uint32_t abase = sbase + sidx * STAGE_BYTES;
        const uint32_t bbase = abase + SM_B_OFF;

#pragma unroll
        for (int ks = 0; ks < 4; ks++) {   // four K=8 steps per KC=32 chunk
            uint32_t af[4][4], bf[4][4];

#pragma unroll
            for (int mt = 0; mt < 4; mt++) {
                const int row = warp_m * 64 + mt * 16 + a_row_l;
                const uint32_t byte = (uint32_t)(row * 128 + ks * 32 + a_k16);
                LDSM_X4(af[mt][0], af[mt][1], af[mt][2], af[mt][3],
                        abase + SMEM_SWIZZLE_128B(byte));
            }
#pragma unroll
            for (int bg = 0; bg < 4; bg++) {      // 4 x 16 n = 64 n
                const int row = warp_n * 64 + bg * 16 + b_row_l;
                const uint32_t byte = (uint32_t)(row * 128 + ks * 32 + b_k16);
                LDSM_X4(bf[bg][0], bf[bg][1], bf[bg][2], bf[bg][3],
                        bbase + SMEM_SWIZZLE_128B(byte));
            }
#pragma unroll
            for (int mt = 0; mt < 4; mt++)
#pragma unroll
                for (int bg = 0; bg < 4; bg++) {
                    MMA_TF32(acc[mt][bg * 2 + 0], af[mt], bf[bg][0], bf[bg][1]);
                    MMA_TF32(acc[mt][bg * 2 + 1], af[mt], bf[bg][2], bf[bg][3]);
                }
        }
        __syncthreads();
        sidx = (sidx + 1 == NSTAGE) ? 0 : sidx + 1;
    }

    // ---- Epilogue: bias + store ----
    const int qrow = lid >> 2;            // 0..7
    const int qcol = (lid & 3) * 2;       // 0,2,4,6
#pragma unroll
    for (int mt = 0; mt < 4; mt++) {
        const int r0 = mrow0 + warp_m * 64 + mt * 16 + qrow;
#pragma unroll
        for (int nb = 0; nb < 8; nb++) {
            const int col = ncol0 + warp_n * 64 + nb * 8 + qcol;
            const float2 bb = *reinterpret_cast<const float2*>(&bias[col]);
            float2 o0, o1;
            o0.x = acc[mt][nb][0] + bb.x;
            o0.y = acc[mt][nb][1] + bb.y;
            o1.x = acc[mt][nb][2] + bb.x;
            o1.y = acc[mt][nb][3] + bb.y;
            *reinterpret_cast<float2*>(&C[(size_t)r0 * OUT_FEATS + col]) = o0;
            *reinterpret_cast<float2*>(&C[(size_t)(r0 + 8) * OUT_FEATS + col]) = o1;
        }
    }
#undef LOAD_STAGE
}

// ---------------------------------------------------------------------------
// Launch: inputs per metadata order: x, phm_rule, W, b. Output float32.
// ---------------------------------------------------------------------------
extern "C" void kernel_launch(void* const* d_in, const int* in_sizes, int n_in,
                              void* d_out, int out_size) {
    const float* x    = (const float*)d_in[0];
    const float* rule = (const float*)d_in[1];
    const float* W    = (const float*)d_in[2];
    const float* b    = (const float*)d_in[3];
    float* y = (float*)d_out;
    (void)in_sizes; (void)n_in; (void)out_size;

    cudaFuncSetAttribute(phm_mma_kernel,
                         cudaFuncAttributeMaxDynamicSharedMemorySize,
                         SMEM_TOTAL_GEMM);

    // 1) round x to tf32 (rna)
    {
        const int total4 = (TOKENS * IN_FEATS) / 4;
        cvt_x_kernel<<<total4 / 256, 256>>>(x);
    }
    // 2) build H^T, tf32-rounded
    {
        dim3 grid(OUT_FEATS / 64, IN_FEATS / 64);   // (128, 32)
        build_Ht_kernel<<<grid, 256>>>(rule, W);
    }
    // 3) tf32 GEMM + bias. M-fast grid -> wave shares B tiles in L2.
    {
        dim3 grid(TOKENS / BM, OUT_FEATS / BN);     // (64, 32)
        phm_mma_kernel<<<grid, NTHREADS, SMEM_TOTAL_GEMM>>>(b, y);
    }
}

// round 16
// speedup vs baseline: 1.6324x; 1.0339x over previous
#include <cuda_runtime.h>
#include <cuda_bf16.h>
#include <cstdint>

// ---------------------------------------------------------------------------
// Problem constants
// ---------------------------------------------------------------------------
#define PHM      4
#define IN_FEATS 2048
#define OUT_FEATS 8192
#define TOKENS   8192
#define IN_PER   (IN_FEATS / PHM)    // 512
#define OUT_PER  (OUT_FEATS / PHM)   // 2048

// ---------------------------------------------------------------------------
// Static device scratch: tf32-rounded (rna) fp32 copies of x and H^T.
// ---------------------------------------------------------------------------
__device__ float g_xt[(size_t)TOKENS * IN_FEATS];                // 64 MB
__device__ float g_Ht[(size_t)OUT_FEATS * IN_FEATS];             // 64 MB, H^T [n][k]

// ---------------------------------------------------------------------------
// Helpers (non-arch-suffixed PTX only)
// ---------------------------------------------------------------------------
__device__ __forceinline__ uint32_t smem_to_u32(const void* p) {
    uint32_t a;
    asm("{ .reg .u64 t; cvta.to.shared.u64 t, %1; cvt.u32.u64 %0, t; }"
        : "=r"(a) : "l"(p));
    return a;
}

__device__ __forceinline__ float f2tf32(float f) {
    float r;
    asm("cvt.rna.tf32.f32 %0, %1;" : "=f"(r) : "f"(f));
    return r;
}

#define SMEM_SWIZZLE_128B(o) ((o) ^ (((o) >> 3) & 0x70))

#define CP_ASYNC16(smem_addr, gptr) \
    asm volatile("cp.async.cg.shared.global [%0], [%1], 16;" \
                 :: "r"((uint32_t)(smem_addr)), "l"(gptr) : "memory")
#define CP_ASYNC_COMMIT() asm volatile("cp.async.commit_group;" ::: "memory")

#define LDSM_X4(r0, r1, r2, r3, addr) \
    asm volatile("ldmatrix.sync.aligned.m8n8.x4.shared.b16 {%0,%1,%2,%3}, [%4];" \
                 : "=r"(r0), "=r"(r1), "=r"(r2), "=r"(r3) : "r"(addr))

// m16n8k8 tf32 MMA: a = 4 regs, b = 2 regs, fp32 accumulate
#define MMA_TF32(d, a, b0, b1) \
    asm volatile("mma.sync.aligned.m16n8k8.row.col.f32.tf32.tf32.f32 " \
                 "{%0,%1,%2,%3}, {%4,%5,%6,%7}, {%8,%9}, {%0,%1,%2,%3};" \
                 : "+f"((d)[0]), "+f"((d)[1]), "+f"((d)[2]), "+f"((d)[3]) \
                 : "r"((a)[0]), "r"((a)[1]), "r"((a)[2]), "r"((a)[3]), \
                   "r"(b0), "r"(b1))

// ---------------------------------------------------------------------------
// Kernel 1: round x to tf32 (rna) — operands must be pre-rounded because the
// MMA's internal mantissa truncation is biased.
// ---------------------------------------------------------------------------
__global__ __launch_bounds__(256) void cvt_x_kernel(const float* __restrict__ x) {
    const size_t i = (size_t)blockIdx.x * 256 + threadIdx.x;  // float4 index
    const float4 v = reinterpret_cast<const float4*>(x)[i];
    float4 o;
    o.x = f2tf32(v.x); o.y = f2tf32(v.y); o.z = f2tf32(v.z); o.w = f2tf32(v.w);
    reinterpret_cast<float4*>(g_xt)[i] = o;
}

// ---------------------------------------------------------------------------
// Kernel 2: build H^T, tf32-rounded fp32.
//   H[r, n] = sum_i rule[i, a, k] * W[i, c, p],  r=a*512+c, n=k*2048+p
// ---------------------------------------------------------------------------
__global__ __launch_bounds__(256) void build_Ht_kernel(
    const float* __restrict__ rule,   // (4,4,4)
    const float* __restrict__ W)      // (4,512,2048)
{
    __shared__ float hs[64][65];

    const int n0 = blockIdx.x * 64;   // over OUT_FEATS
    const int r0 = blockIdx.y * 64;   // over IN_FEATS
    const int a = r0 >> 9;
    const int k = n0 >> 11;

    const float s0 = rule[0 * 16 + a * 4 + k];
    const float s1 = rule[1 * 16 + a * 4 + k];
    const float s2 = rule[2 * 16 + a * 4 + k];
    const float s3 = rule[3 * 16 + a * 4 + k];

    {
        const int nl = threadIdx.x & 63;
        const int rg = threadIdx.x >> 6;    // 0..3
        const int p = (n0 & 2047) + nl;
        const int cbase = (r0 & 511);
#pragma unroll
        for (int j = 0; j < 16; j++) {
            const int rl = rg * 16 + j;
            const int c = cbase + rl;
            float acc = s0 * W[(size_t)(0 * IN_PER + c) * OUT_PER + p]
                      + s1 * W[(size_t)(1 * IN_PER + c) * OUT_PER + p]
                      + s2 * W[(size_t)(2 * IN_PER + c) * OUT_PER + p]
                      + s3 * W[(size_t)(3 * IN_PER + c) * OUT_PER + p];
            hs[rl][nl] = acc;
        }
    }
    __syncthreads();
    {
        const int rl = threadIdx.x & 63;
        const int ng = threadIdx.x >> 6;
#pragma unroll
        for (int j = 0; j < 16; j++) {
            const int nn = ng * 16 + j;
            g_Ht[(size_t)(n0 + nn) * IN_FEATS + r0 + rl] = f2tf32(hs[rl][nn]);
        }
    }
}

// ---------------------------------------------------------------------------
// Kernel 3: tf32 MMA GEMM, y = x @ H + b.
//   Identical tiling to R15 (128x256x32, 3-stage, 8 warps, 64x64 warp tile);
//   ONLY change: register-level double-buffered fragments — load ks+1's
//   ldmatrix fragments BEFORE issuing ks's MMAs so the smem crossbar and the
//   tensor pipe overlap instead of alternating.
// ---------------------------------------------------------------------------
#define BM 128
#define BN 256
#define KC 32
#define NSTAGE 3
#define NTHREADS 256
#define NCHUNK (IN_FEATS / KC)              // 64
#define SM_B_OFF (BM * 128)                 // 16 KB
#define STAGE_BYTES ((BM + BN) * 128)       // 48 KB
#define SMEM_TOTAL_GEMM (NSTAGE * STAGE_BYTES)  // 144 KB

__global__ __launch_bounds__(NTHREADS, 1) void phm_mma_kernel(
    const float* __restrict__ bias,
    float* __restrict__ C)
{
    extern __shared__ char smem[];
    const uint32_t sbase = smem_to_u32(smem);
    const int tid = threadIdx.x;
    const int lid = tid & 31;
    const int wid = tid >> 5;
    const int warp_m = wid & 1;       // 2 warps over M (64 rows each)
    const int warp_n = wid >> 1;      // 4 warps over N (64 cols each)

    const int mrow0 = blockIdx.x * BM;
    const int ncol0 = blockIdx.y * BN;

    float acc[4][8][4];               // [mt][n8-group][frag]
#pragma unroll
    for (int i = 0; i < 4; i++)
#pragma unroll
        for (int j = 0; j < 8; j++)
#pragma unroll
            for (int e = 0; e < 4; e++) acc[i][j][e] = 0.f;

    // ---- stage loader: A 128 rows x 128B, B 256 rows x 128B (16B units) ----
#define LOAD_STAGE(sptr, c) do {                                              \
    const int _kc0 = (c) * KC;                                                \
    _Pragma("unroll")                                                         \
    for (int _j = 0; _j < 4; _j++) {                                          \
        const int _q = tid + NTHREADS * _j;                                   \
        const int _row = _q >> 3; const int _u = _q & 7;                      \
        const uint32_t _so = (sptr) +                                         \
            SMEM_SWIZZLE_128B((uint32_t)(_row * 128 + _u * 16));              \
        CP_ASYNC16(_so, g_xt + (size_t)(mrow0 + _row) * IN_FEATS + _kc0 + _u * 4); \
    }                                                                         \
    _Pragma("unroll")                                                         \
    for (int _j = 0; _j < 8; _j++) {                                          \
        const int _q = tid + NTHREADS * _j;                                   \
        const int _row = _q >> 3; const int _u = _q & 7;                      \
        const uint32_t _so = (sptr) + SM_B_OFF +                              \
            SMEM_SWIZZLE_128B((uint32_t)(_row * 128 + _u * 16));              \
        CP_ASYNC16(_so, g_Ht + (size_t)(ncol0 + _row) * IN_FEATS + _kc0 + _u * 4); \
    }                                                                         \
    CP_ASYNC_COMMIT();                                                        \
} while (0)

    // Fragment loader for one K=8 step from stage base (abase_, bbase_)
#define LOAD_FRAGS(af_, bf_, abase_, bbase_, ks_) do {                        \
    _Pragma("unroll")                                                         \
    for (int _mt = 0; _mt < 4; _mt++) {                                       \
        const int _row = warp_m * 64 + _mt * 16 + a_row_l;                    \
        const uint32_t _byte = (uint32_t)(_row * 128 + (ks_) * 32 + a_k16);   \
        LDSM_X4((af_)[_mt][0], (af_)[_mt][1], (af_)[_mt][2], (af_)[_mt][3],   \
                (abase_) + SMEM_SWIZZLE_128B(_byte));                         \
    }                                                                         \
    _Pragma("unroll")                                                         \
    for (int _bg = 0; _bg < 4; _bg++) {                                       \
        const int _row = warp_n * 64 + _bg * 16 + b_row_l;                    \
        const uint32_t _byte = (uint32_t)(_row * 128 + (ks_) * 32 + b_k16);   \
        LDSM_X4((bf_)[_bg][0], (bf_)[_bg][1], (bf_)[_bg][2], (bf_)[_bg][3],   \
                (bbase_) + SMEM_SWIZZLE_128B(_byte));                         \
    }                                                                         \
} while (0)

#define DO_MMAS(af_, bf_) do {                                                \
    _Pragma("unroll")                                                         \
    for (int _mt = 0; _mt < 4; _mt++)                                         \
        _Pragma("unroll")                                                     \
        for (int _bg = 0; _bg < 4; _bg++) {                                   \
            MMA_TF32(acc[_mt][_bg * 2 + 0], (af_)[_mt], (bf_)[_bg][0], (bf_)[_bg][1]); \
            MMA_TF32(acc[_mt][_bg * 2 + 1], (af_)[_mt], (bf_)[_bg][2], (bf_)[_bg][3]); \
        }                                                                     \
} while (0)

    // Prologue
    LOAD_STAGE(sbase + 0 * STAGE_BYTES, 0);
    LOAD_STAGE(sbase + 1 * STAGE_BYTES, 1);

    // ldmatrix lane addressing
    const int a_row_l = lid & 15;
    const int a_k16   = (lid >> 4) * 16;
    const int b_row_l = ((lid >> 4) << 3) + (lid & 7);
    const int b_k16   = ((lid >> 3) & 1) * 16;

    uint32_t af[2][4][4], bf[2][4][4];   // double-buffered fragments

    int sidx = 0;
    for (int c = 0; c < NCHUNK; c++) {
        if (c + 1 < NCHUNK) {
            asm volatile("cp.async.wait_group 1;" ::: "memory");
        } else {
            asm volatile("cp.async.wait_group 0;" ::: "memory");
        }
        __syncthreads();

        if (c + 2 < NCHUNK) {
            const int ns = (sidx + 2 >= NSTAGE) ? (sidx + 2 - NSTAGE) : (sidx + 2);
            LOAD_STAGE(sbase + ns * STAGE_BYTES, c + 2);
        }

        const uint32_t abase = sbase + sidx * STAGE_BYTES;
        const uint32_t bbase = abase + SM_B_OFF;

        // ks-software-pipeline: frags for ks+1 issue before MMAs of ks.
        LOAD_FRAGS(af[0], bf[0], abase, bbase, 0);
        LOAD_FRAGS(af[1], bf[1], abase, bbase, 1);
        DO_MMAS(af[0], bf[0]);
        LOAD_FRAGS(af[0], bf[0], abase, bbase, 2);
        DO_MMAS(af[1], bf[1]);
        LOAD_FRAGS(af[1], bf[1], abase, bbase, 3);
        DO_MMAS(af[0], bf[0]);
        DO_MMAS(af[1], bf[1]);

        __syncthreads();
        sidx = (sidx + 1 == NSTAGE) ? 0 : sidx + 1;
    }

    // ---- Epilogue: bias + store ----
    const int qrow = lid >> 2;            // 0..7
    const int qcol = (lid & 3) * 2;       // 0,2,4,6
#pragma unroll
    for (int mt = 0; mt < 4; mt++) {
        const int r0 = mrow0 + warp_m * 64 + mt * 16 + qrow;
#pragma unroll
        for (int nb = 0; nb < 8; nb++) {
            const int col = ncol0 + warp_n * 64 + nb * 8 + qcol;
            const float2 bb = *reinterpret_cast<const float2*>(&bias[col]);
            float2 o0, o1;
            o0.x = acc[mt][nb][0] + bb.x;
            o0.y = acc[mt][nb][1] + bb.y;
            o1.x = acc[mt][nb][2] + bb.x;
            o1.y = acc[mt][nb][3] + bb.y;
            *reinterpret_cast<float2*>(&C[(size_t)r0 * OUT_FEATS + col]) = o0;
            *reinterpret_cast<float2*>(&C[(size_t)(r0 + 8) * OUT_FEATS + col]) = o1;
        }
    }
#undef LOAD_STAGE
#undef LOAD_FRAGS
#undef DO_MMAS
}

// ---------------------------------------------------------------------------
// Launch: inputs per metadata order: x, phm_rule, W, b. Output float32.
// ---------------------------------------------------------------------------
extern "C" void kernel_launch(void* const* d_in, const int* in_sizes, int n_in,
                              void* d_out, int out_size) {
    const float* x    = (const float*)d_in[0];
    const float* rule = (const float*)d_in[1];
    const float* W    = (const float*)d_in[2];
    const float* b    = (const float*)d_in[3];
    float* y = (float*)d_out;
    (void)in_sizes; (void)n_in; (void)out_size;

    cudaFuncSetAttribute(phm_mma_kernel,
                         cudaFuncAttributeMaxDynamicSharedMemorySize,
                         SMEM_TOTAL_GEMM);

    // 1) round x to tf32 (rna)
    {
        const int total4 = (TOKENS * IN_FEATS) / 4;
        cvt_x_kernel<<<total4 / 256, 256>>>(x);
    }
    // 2) build H^T, tf32-rounded
    {
        dim3 grid(OUT_FEATS / 64, IN_FEATS / 64);   // (128, 32)
        build_Ht_kernel<<<grid, 256>>>(rule, W);
    }
    // 3) tf32 GEMM + bias. M-fast grid -> wave shares B tiles in L2.
    {
        dim3 grid(TOKENS / BM, OUT_FEATS / BN);     // (64, 32)
        phm_mma_kernel<<<grid, NTHREADS, SMEM_TOTAL_GEMM>>>(b, y);
    }
}